// round 15
// baseline (speedup 1.0000x reference)
#include <cuda_runtime.h>
#include <cuda_fp16.h>
#include <math.h>
#include <stdint.h>

// Problem constants
#define LNUM 2
#define HNUM 16
#define DMODEL 1024
#define FF 4096
#define BATCH 2
#define SEQ 2048
#define LN_EPS 1e-5f

#define ROWS (BATCH * SEQ)          // 4096
#define BH (BATCH * HNUM)           // 32
#define QKVN 3072

// per-layer transposed-weight layout inside g_w (in halves)
#define OFF_QKV 0
#define OFF_WO  (3u * 1024u * 1024u)
#define OFF_W1  (4u * 1024u * 1024u)
#define OFF_W2  (8u * 1024u * 1024u)
#define LW      (12u * 1024u * 1024u)

// ---------------- device scratch ----------------
__device__ float g_buf0[(size_t)ROWS * DMODEL];
__device__ float g_buf1[(size_t)ROWS * DMODEL];

__device__ __half g_h  [(size_t)ROWS * DMODEL];
__device__ __half g_qkv[(size_t)ROWS * QKVN];
__device__ __half g_ao [(size_t)ROWS * DMODEL];
__device__ __half g_ff [(size_t)ROWS * FF];
__device__ __half g_w  [(size_t)LNUM * LW];     // 24M halves = 48 MB

// ---------------- helpers ----------------
__device__ __forceinline__ uint32_t smem_u32(const void* p) {
    uint32_t a;
    asm("{ .reg .u64 t; cvta.to.shared.u64 t, %1; cvt.u32.u64 %0, t; }"
        : "=r"(a) : "l"(p));
    return a;
}

__device__ __forceinline__ void cp16(uint32_t dst, const void* src) {
    asm volatile("cp.async.cg.shared.global [%0], [%1], 16;"
                 :: "r"(dst), "l"(src));
}

__device__ __forceinline__ void ldm_x4(uint32_t addr, uint32_t r[4]) {
    asm volatile("ldmatrix.sync.aligned.m8n8.x4.shared.b16 {%0,%1,%2,%3}, [%4];"
                 : "=r"(r[0]), "=r"(r[1]), "=r"(r[2]), "=r"(r[3]) : "r"(addr));
}

__device__ __forceinline__ void ldm_x4_t(uint32_t addr, uint32_t r[4]) {
    asm volatile("ldmatrix.sync.aligned.m8n8.x4.trans.shared.b16 {%0,%1,%2,%3}, [%4];"
                 : "=r"(r[0]), "=r"(r[1]), "=r"(r[2]), "=r"(r[3]) : "r"(addr));
}

__device__ __forceinline__ void mma_f16(float d[4], const uint32_t a[4],
                                        const uint32_t b[2]) {
    asm volatile(
        "mma.sync.aligned.m16n8k16.row.col.f32.f16.f16.f32 "
        "{%0,%1,%2,%3}, {%4,%5,%6,%7}, {%8,%9}, {%0,%1,%2,%3};"
        : "+f"(d[0]), "+f"(d[1]), "+f"(d[2]), "+f"(d[3])
        : "r"(a[0]), "r"(a[1]), "r"(a[2]), "r"(a[3]), "r"(b[0]), "r"(b[1]));
}

__device__ __forceinline__ uint32_t pack_h2(float a, float b) {
    __half2 t = __floats2half2_rn(a, b);
    return *(uint32_t*)&t;
}

__device__ __forceinline__ void hstore2(__half* p, size_t off, float v0, float v1) {
    *(__half2*)(p + off) = __floats2half2_rn(v0, v1);
}

__device__ __forceinline__ float ex2f(float x) {
    float y;
    asm("ex2.approx.ftz.f32 %0, %1;" : "=f"(y) : "f"(x));
    return y;
}

#define CP_COMMIT() asm volatile("cp.async.commit_group;" ::: "memory")

// ---------------- batched weight transpose-cast (all layers, one launch) ----------------
#define NSEG 12

struct CastTable {
    const float* in[NSEG];
    long long outOff[NSEG];
    int Kdim[NSEG];
    int Ndim[NSEG];
    int tile0[NSEG];
};

__global__ void __launch_bounds__(256)
castAll_kernel(CastTable tab, __half* __restrict__ outBase)
{
    __shared__ float t[64][65];
    const int bid = blockIdx.x;
    int s = 0;
#pragma unroll
    for (int i = 1; i < NSEG; i++)
        if (bid >= tab.tile0[i]) s = i;

    const float* in = tab.in[s];
    __half* outT = outBase + tab.outOff[s];
    const int Kdim = tab.Kdim[s], Ndim = tab.Ndim[s];
    const int lt = bid - tab.tile0[s];
    const int tiles_x = Ndim >> 6;
    const int n0 = (lt % tiles_x) * 64, k0 = (lt / tiles_x) * 64;

    {
        const int tx = threadIdx.x & 15, ty = threadIdx.x >> 4;
#pragma unroll
        for (int j = 0; j < 4; j++) {
            const int k = ty + j * 16;
            float4 v = *(const float4*)(in + (size_t)(k0 + k) * Ndim + n0 + tx * 4);
            t[k][tx * 4 + 0] = v.x;
            t[k][tx * 4 + 1] = v.y;
            t[k][tx * 4 + 2] = v.z;
            t[k][tx * 4 + 3] = v.w;
        }
    }
    __syncthreads();
    {
        const int tx = threadIdx.x & 31, ty = threadIdx.x >> 5;
#pragma unroll
        for (int j = 0; j < 8; j++) {
            const int n = ty + j * 8;
            __half2 h = __floats2half2_rn(t[tx * 2][n], t[tx * 2 + 1][n]);
            *(__half2*)(outT + (size_t)(n0 + n) * Kdim + k0 + tx * 2) = h;
        }
    }
}

// ---------------- fp16 tensor-core GEMM, 4-stage cp.async ring, K-chunk 32 ----------------
// OMODE 0: Cf = acc + bias (+res), fp32.   OMODE 1: Ch = fp16(scl*(relu?(acc+bias))).
#define TILEB (128 * 80)               // 10240 B
#define STAGEB (2 * TILEB)             // 20480 B
#define GSMEM (4 * STAGEB)             // 81920 B

template <int OMODE>
__global__ void __launch_bounds__(256, 2)
mma_gemm(const __half* __restrict__ A, const __half* __restrict__ B,
         const float* __restrict__ bias0, const float* __restrict__ bias1,
         const float* __restrict__ bias2, int biasSeg, float scl0,
         const float* __restrict__ res,
         float* __restrict__ Cf, __half* __restrict__ Ch,
         int M, int N, int K, int relu)
{
    extern __shared__ char smem[];
    const uint32_t sb = smem_u32(smem);

    const int tid = threadIdx.x, wid = tid >> 5, lane = tid & 31;
    const int bm = blockIdx.y * 128, bn = blockIdx.x * 128;
    const int wm = wid >> 2, wn = wid & 3;     // warp tile 64 x 32

    const __half* sA = A + (size_t)bm * K;
    const __half* sB = B + (size_t)bn * K;

    const int r0 = (tid * 2) >> 2, c0 = (tid * 2) & 3;
    const int r1 = (tid * 2 + 1) >> 2, c1 = (tid * 2 + 1) & 3;

    const int NC = K >> 5;

#define ISSUE_CHUNK(c)                                                      \
    do {                                                                    \
        const uint32_t st_ = sb + ((c) & 3) * STAGEB;                       \
        const int kc_ = (c) << 5;                                           \
        cp16(st_ + r0 * 80 + c0 * 16, sA + (size_t)r0 * K + kc_ + c0 * 8);  \
        cp16(st_ + r1 * 80 + c1 * 16, sA + (size_t)r1 * K + kc_ + c1 * 8);  \
        cp16(st_ + TILEB + r0 * 80 + c0 * 16,                               \
             sB + (size_t)r0 * K + kc_ + c0 * 8);                           \
        cp16(st_ + TILEB + r1 * 80 + c1 * 16,                               \
             sB + (size_t)r1 * K + kc_ + c1 * 8);                           \
        CP_COMMIT();                                                        \
    } while (0)

    ISSUE_CHUNK(0);
    ISSUE_CHUNK(1);
    ISSUE_CHUNK(2);

    float d[4][4][4];
#pragma unroll
    for (int i = 0; i < 4; i++)
#pragma unroll
        for (int j = 0; j < 4; j++)
#pragma unroll
            for (int q = 0; q < 4; q++) d[i][j][q] = 0.f;

    const uint32_t arow = (uint32_t)(wm * 64 + (lane & 15));
    const uint32_t abyte = (uint32_t)((lane >> 4) * 16);
    const uint32_t bnr = (uint32_t)(wn * 32 + (lane & 7) + 8 * ((lane >> 4) & 1));
    const uint32_t bkb = (uint32_t)(((lane >> 3) & 1) * 16);

    for (int c = 0; c < NC; c++) {
        if (c + 3 <= NC) {
            asm volatile("cp.async.wait_group 2;" ::: "memory");
        } else if (c + 2 == NC) {
            asm volatile("cp.async.wait_group 1;" ::: "memory");
        } else {
            asm volatile("cp.async.wait_group 0;" ::: "memory");
        }
        __syncthreads();
        if (c + 3 < NC) ISSUE_CHUNK(c + 3);

        const uint32_t st = sb + (c & 3) * STAGEB;
#pragma unroll
        for (int k16 = 0; k16 < 2; k16++) {
            uint32_t af[4][4], bfr[4][2];
#pragma unroll
            for (int i = 0; i < 4; i++)
                ldm_x4(st + (arow + i * 16) * 80 + k16 * 32 + abyte, af[i]);
#pragma unroll
            for (int nb = 0; nb < 2; nb++) {
                uint32_t r[4];
                ldm_x4(st + TILEB + (bnr + nb * 16) * 80 + k16 * 32 + bkb, r);
                bfr[nb * 2 + 0][0] = r[0]; bfr[nb * 2 + 0][1] = r[1];
                bfr[nb * 2 + 1][0] = r[2]; bfr[nb * 2 + 1][1] = r[3];
            }
#pragma unroll
            for (int i = 0; i < 4; i++)
#pragma unroll
                for (int j = 0; j < 4; j++)
                    mma_f16(d[i][j], af[i], bfr[j]);
        }
    }
#undef ISSUE_CHUNK

    // epilogue
    const int seg = bn / biasSeg;
    const float* bp = (seg == 0) ? bias0 : ((seg == 1) ? bias1 : bias2);
    const float scl = (seg == 0) ? scl0 : 1.f;
    const int bcol0 = bn - seg * biasSeg;
    const int er = lane >> 2, ec = 2 * (lane & 3);
#pragma unroll
    for (int i = 0; i < 4; i++) {
#pragma unroll
        for (int rr = 0; rr < 2; rr++) {
            const int grow = bm + wm * 64 + i * 16 + er + rr * 8;
#pragma unroll
            for (int j = 0; j < 4; j++) {
                const int coff = wn * 32 + j * 8 + ec;
                const int gcol = bn + coff;
                float v0 = d[i][j][rr * 2 + 0] + bp[bcol0 + coff];
                float v1 = d[i][j][rr * 2 + 1] + bp[bcol0 + coff + 1];
                if (relu) { v0 = fmaxf(v0, 0.f); v1 = fmaxf(v1, 0.f); }
                if (OMODE == 0) {
                    if (res) {
                        v0 += res[(size_t)grow * N + gcol];
                        v1 += res[(size_t)grow * N + gcol + 1];
                    }
                    *(float2*)(Cf + (size_t)grow * N + gcol) = make_float2(v0, v1);
                } else {
                    hstore2(Ch, (size_t)grow * N + gcol, v0 * scl, v1 * scl);
                }
            }
        }
    }
}

// ---------------- LayerNorm -> fp16 ----------------
__global__ void __launch_bounds__(256)
ln_h_kernel(const float* __restrict__ in, const float* __restrict__ gamma,
            const float* __restrict__ beta, __half* __restrict__ out)
{
    const int row = blockIdx.x;
    const float* x = in + (size_t)row * DMODEL;
    const int tid = threadIdx.x;

    float4 v4 = *(const float4*)(x + tid * 4);
    float v[4] = {v4.x, v4.y, v4.z, v4.w};
    float s = 0.f, ss = 0.f;
#pragma unroll
    for (int j = 0; j < 4; j++) { s += v[j]; ss += v[j] * v[j]; }
#pragma unroll
    for (int o2 = 16; o2 > 0; o2 >>= 1) {
        s  += __shfl_xor_sync(0xffffffffu, s,  o2);
        ss += __shfl_xor_sync(0xffffffffu, ss, o2);
    }
    __shared__ float red[18];
    const int warp = tid >> 5, lane = tid & 31;
    if (lane == 0) { red[warp] = s; red[warp + 8] = ss; }
    __syncthreads();
    if (tid == 0) {
        float ts = 0.f, tss = 0.f;
#pragma unroll
        for (int w = 0; w < 8; w++) { ts += red[w]; tss += red[w + 8]; }
        float mu = ts / (float)DMODEL;
        float var = tss / (float)DMODEL - mu * mu;
        red[16] = mu;
        red[17] = rsqrtf(var + LN_EPS);
    }
    __syncthreads();
    const float mu = red[16], rstd = red[17];
    float y[4];
#pragma unroll
    for (int j = 0; j < 4; j++) {
        int idx = tid * 4 + j;
        y[j] = (v[j] - mu) * rstd * gamma[idx] + beta[idx];
    }
    hstore2(out, (size_t)row * DMODEL + tid * 4,     y[0], y[1]);
    hstore2(out, (size_t)row * DMODEL + tid * 4 + 2, y[2], y[3]);
}

// ---------------- Final LayerNorm (fp32 out) ----------------
__global__ void __launch_bounds__(256)
ln_kernel(const float* __restrict__ in, const float* __restrict__ gamma,
          const float* __restrict__ beta, float* __restrict__ out)
{
    const int row = blockIdx.x;
    const float* x = in + (size_t)row * DMODEL;
    float* o = out + (size_t)row * DMODEL;
    const int tid = threadIdx.x;

    float v[4];
    float s = 0.f, ss = 0.f;
#pragma unroll
    for (int j = 0; j < 4; j++) {
        v[j] = x[tid + j * 256];
        s += v[j];
        ss += v[j] * v[j];
    }
#pragma unroll
    for (int o2 = 16; o2 > 0; o2 >>= 1) {
        s  += __shfl_xor_sync(0xffffffffu, s,  o2);
        ss += __shfl_xor_sync(0xffffffffu, ss, o2);
    }
    __shared__ float red[18];
    const int warp = tid >> 5, lane = tid & 31;
    if (lane == 0) { red[warp] = s; red[warp + 8] = ss; }
    __syncthreads();
    if (tid == 0) {
        float ts = 0.f, tss = 0.f;
#pragma unroll
        for (int w = 0; w < 8; w++) { ts += red[w]; tss += red[w + 8]; }
        float mu = ts / (float)DMODEL;
        float var = tss / (float)DMODEL - mu * mu;
        red[16] = mu;
        red[17] = rsqrtf(var + LN_EPS);
    }
    __syncthreads();
    const float mu = red[16], rstd = red[17];
#pragma unroll
    for (int j = 0; j < 4; j++) {
        int idx = tid + j * 256;
        o[idx] = (v[j] - mu) * rstd * gamma[idx] + beta[idx];
    }
}

// ---------------- Flash attention: Q-block 64, 128 threads, 5 CTA/SM target ----------------
// Q pre-scaled (log2 domain). smem: Q 64x144 = 9216; 2 stages of (K 9216 + V 9216).
#define F_STG 9216
#define F_STGB 18432
#define FLASH_SMEM (F_STG + 2 * F_STGB)   // 46080

__global__ void __launch_bounds__(128, 5)
flash_mma(const __half* __restrict__ qkv, __half* __restrict__ ao)
{
    extern __shared__ char smem[];
    const uint32_t sb = smem_u32(smem);

    const int qb = blockIdx.x, bh = blockIdx.y;
    const int b = bh >> 4, h = bh & 15;
    const int tid = threadIdx.x, wid = tid >> 5, lane = tid & 31;

    const size_t qrow0 = (size_t)b * SEQ + (size_t)qb * 64;
    const __half* qp = qkv + qrow0 * QKVN + h * 64;
    const __half* kp = qkv + (size_t)b * SEQ * QKVN + 1024 + h * 64;
    const __half* vp = qkv + (size_t)b * SEQ * QKVN + 2048 + h * 64;

    // stage Q (64 rows x 8 chunks = 512 cp16 over 128 threads)
#pragma unroll
    for (int it = 0; it < 4; it++) {
        int f = tid + it * 128;
        int r = f >> 3, ch = f & 7;
        cp16(sb + r * 144 + ch * 16, qp + (size_t)r * QKVN + ch * 8);
    }
    // stage K/V tile 0
#pragma unroll
    for (int it = 0; it < 4; it++) {
        int f = tid + it * 128;
        int r = f >> 3, ch = f & 7;
        uint32_t dst = sb + F_STG + r * 144 + ch * 16;
        size_t go = (size_t)r * QKVN + ch * 8;
        cp16(dst, kp + go);
        cp16(dst + 9216, vp + go);
    }
    CP_COMMIT();

    float o[8][4];
#pragma unroll
    for (int j = 0; j < 8; j++)
#pragma unroll
        for (int q = 0; q < 4; q++) o[j][q] = 0.f;
    float m0 = -INFINITY, m1 = -INFINITY, l0 = 0.f, l1 = 0.f;

    const uint32_t aq_row = sb + (wid * 16 + (lane & 15)) * 144;
    const uint32_t acol = (uint32_t)(16 * (lane >> 4));
    const uint32_t bn_row = (uint32_t)(((lane & 7) + 8 * ((lane >> 4) & 1)) * 144);
    const uint32_t bkb = (uint32_t)(16 * ((lane >> 3) & 1));
    const uint32_t v_row = (uint32_t)(((lane & 7) + 8 * ((lane >> 3) & 1)) * 144);
    const uint32_t v_db = (uint32_t)(16 * ((lane >> 4) & 1));

    for (int kt = 0; kt < SEQ / 64; kt++) {
        asm volatile("cp.async.wait_group 0;" ::: "memory");
        __syncthreads();

        if (kt + 1 < SEQ / 64) {
            uint32_t st = sb + F_STG + ((kt + 1) & 1) * F_STGB;
            size_t rbase = (size_t)(kt + 1) * 64;
#pragma unroll
            for (int it = 0; it < 4; it++) {
                int f = tid + it * 128;
                int r = f >> 3, ch = f & 7;
                uint32_t dst = st + r * 144 + ch * 16;
                size_t go = (rbase + r) * QKVN + ch * 8;
                cp16(dst, kp + go);
                cp16(dst + 9216, vp + go);
            }
            CP_COMMIT();
        }

        const uint32_t kst = sb + F_STG + (kt & 1) * F_STGB;

        // ---- S = Q K^T (Q pre-scaled, log2 domain) ----
        float s[8][4];
#pragma unroll
        for (int j = 0; j < 8; j++)
#pragma unroll
            for (int q = 0; q < 4; q++) s[j][q] = 0.f;

#pragma unroll
        for (int t = 0; t < 4; t++) {
            uint32_t af[4];
            ldm_x4(aq_row + t * 32 + acol, af);
            uint32_t kbase = kst + bn_row + t * 32 + bkb;
#pragma unroll
            for (int nb = 0; nb < 4; nb++) {
                uint32_t r[4];
                ldm_x4(kbase + nb * 16 * 144, r);
                mma_f16(s[nb * 2],     af, &r[0]);
                mma_f16(s[nb * 2 + 1], af, &r[2]);
            }
        }

        // ---- online softmax (base-2, pre-scaled) ----
        float mx0 = -INFINITY, mx1 = -INFINITY;
#pragma unroll
        for (int j = 0; j < 8; j++) {
            mx0 = fmaxf(mx0, fmaxf(s[j][0], s[j][1]));
            mx1 = fmaxf(mx1, fmaxf(s[j][2], s[j][3]));
        }
        mx0 = fmaxf(mx0, __shfl_xor_sync(0xffffffffu, mx0, 1));
        mx0 = fmaxf(mx0, __shfl_xor_sync(0xffffffffu, mx0, 2));
        mx1 = fmaxf(mx1, __shfl_xor_sync(0xffffffffu, mx1, 1));
        mx1 = fmaxf(mx1, __shfl_xor_sync(0xffffffffu, mx1, 2));
        const float mn0 = fmaxf(m0, mx0), mn1 = fmaxf(m1, mx1);
        const float c0 = ex2f(m0 - mn0), c1 = ex2f(m1 - mn1);
        float rs0 = 0.f, rs1 = 0.f;
#pragma unroll
        for (int j = 0; j < 8; j++) {
            s[j][0] = ex2f(s[j][0] - mn0);
            s[j][1] = ex2f(s[j][1] - mn0);
            s[j][2] = ex2f(s[j][2] - mn1);
            s[j][3] = ex2f(s[j][3] - mn1);
            rs0 += s[j][0] + s[j][1];
            rs1 += s[j][2] + s[j][3];
        }
        rs0 += __shfl_xor_sync(0xffffffffu, rs0, 1);
        rs0 += __shfl_xor_sync(0xffffffffu, rs0, 2);
        rs1 += __shfl_xor_sync(0xffffffffu, rs1, 1);
        rs1 += __shfl_xor_sync(0xffffffffu, rs1, 2);
        if (c0 != 1.f) {
            l0 *= c0;
#pragma unroll
            for (int j = 0; j < 8; j++) { o[j][0] *= c0; o[j][1] *= c0; }
        }
        if (c1 != 1.f) {
            l1 *= c1;
#pragma unroll
            for (int j = 0; j < 8; j++) { o[j][2] *= c1; o[j][3] *= c1; }
        }
        l0 += rs0;
        l1 += rs1;
        m0 = mn0; m1 = mn1;

        // ---- O += P V ----
        const uint32_t vst = kst + 9216;
#pragma unroll
        for (int t = 0; t < 4; t++) {
            uint32_t pa[4];
            pa[0] = pack_h2(s[2 * t][0],     s[2 * t][1]);
            pa[1] = pack_h2(s[2 * t][2],     s[2 * t][3]);
            pa[2] = pack_h2(s[2 * t + 1][0], s[2 * t + 1][1]);
            pa[3] = pack_h2(s[2 * t + 1][2], s[2 * t + 1][3]);
            uint32_t vbase = vst + t * 16 * 144 + v_row + v_db;
#pragma unroll
            for (int nb = 0; nb < 4; nb++) {
                uint32_t r[4];
                ldm_x4_t(vbase + nb * 32, r);
                mma_f16(o[nb * 2],     pa, &r[0]);
                mma_f16(o[nb * 2 + 1], pa, &r[2]);
            }
        }
    }

    const float inv0 = 1.f / l0, inv1 = 1.f / l1;
    const size_t row0 = qrow0 + wid * 16 + (lane >> 2);
    const int colb = h * 64 + 2 * (lane & 3);
#pragma unroll
    for (int j = 0; j < 8; j++) {
        hstore2(ao, row0 * DMODEL + colb + j * 8,       o[j][0] * inv0, o[j][1] * inv0);
        hstore2(ao, (row0 + 8) * DMODEL + colb + j * 8, o[j][2] * inv1, o[j][3] * inv1);
    }
}

// ---------------- host orchestration ----------------
extern "C" void kernel_launch(void* const* d_in, const int* in_sizes, int n_in,
                              void* d_out, int out_size)
{
    (void)in_sizes; (void)n_in; (void)out_size;
    const float* x    = (const float*)d_in[0];
    const float* Wq   = (const float*)d_in[1];
    const float* bq   = (const float*)d_in[2];
    const float* Wk   = (const float*)d_in[3];
    const float* bk   = (const float*)d_in[4];
    const float* Wv   = (const float*)d_in[5];
    const float* bv   = (const float*)d_in[6];
    const float* Wo   = (const float*)d_in[7];
    const float* bo   = (const float*)d_in[8];
    const float* W1   = (const float*)d_in[9];
    const float* b1   = (const float*)d_in[10];
    const float* W2   = (const float*)d_in[11];
    const float* b2   = (const float*)d_in[12];
    const float* gin  = (const float*)d_in[13];
    const float* bin  = (const float*)d_in[14];
    const float* gat  = (const float*)d_in[15];
    const float* bat  = (const float*)d_in[16];
    const float* gou  = (const float*)d_in[17];
    const float* bou  = (const float*)d_in[18];
    float* out = (float*)d_out;

    cudaFuncSetAttribute(mma_gemm<0>,
                         cudaFuncAttributeMaxDynamicSharedMemorySize, GSMEM);
    cudaFuncSetAttribute(mma_gemm<1>,
                         cudaFuncAttributeMaxDynamicSharedMemorySize, GSMEM);
    cudaFuncSetAttribute(flash_mma,
                         cudaFuncAttributeMaxDynamicSharedMemorySize, FLASH_SMEM);

    float *p_b0, *p_b1;
    __half *p_h, *p_qkv, *p_ao, *p_ff, *p_w;
    cudaGetSymbolAddress((void**)&p_b0,  g_buf0);
    cudaGetSymbolAddress((void**)&p_b1,  g_buf1);
    cudaGetSymbolAddress((void**)&p_h,   g_h);
    cudaGetSymbolAddress((void**)&p_qkv, g_qkv);
    cudaGetSymbolAddress((void**)&p_ao,  g_ao);
    cudaGetSymbolAddress((void**)&p_ff,  g_ff);
    cudaGetSymbolAddress((void**)&p_w,   g_w);

    // ---- one batched transpose-cast for ALL weights of BOTH layers ----
    {
        CastTable tab;
        int t0 = 0;
        for (int l = 0; l < LNUM; l++) {
            const int base = l * 6;
            const float* wsrc[6] = {
                Wq + (size_t)l * DMODEL * DMODEL,
                Wk + (size_t)l * DMODEL * DMODEL,
                Wv + (size_t)l * DMODEL * DMODEL,
                Wo + (size_t)l * DMODEL * DMODEL,
                W1 + (size_t)l * DMODEL * FF,
                W2 + (size_t)l * FF * DMODEL };
            const long long woff[6] = {
                (long long)l * LW + OFF_QKV,
                (long long)l * LW + OFF_QKV + (long long)DMODEL * DMODEL,
                (long long)l * LW + OFF_QKV + 2LL * DMODEL * DMODEL,
                (long long)l * LW + OFF_WO,
                (long long)l * LW + OFF_W1,
                (long long)l * LW + OFF_W2 };
            const int kk[6] = {DMODEL, DMODEL, DMODEL, DMODEL, DMODEL, FF};
            const int nn[6] = {DMODEL, DMODEL, DMODEL, DMODEL, FF, DMODEL};
            for (int i = 0; i < 6; i++) {
                tab.in[base + i] = wsrc[i];
                tab.outOff[base + i] = woff[i];
                tab.Kdim[base + i] = kk[i];
                tab.Ndim[base + i] = nn[i];
                tab.tile0[base + i] = t0;
                t0 += (kk[i] >> 6) * (nn[i] >> 6);
            }
        }
        castAll_kernel<<<t0, 256>>>(tab, p_w);
    }

    // residual rotation: layer-0 residual read directly from x (no memcpy)
    const float* cur = x;
    float* bufs[2] = {p_b0, p_b1};
    int bi = 0;

    const dim3 gQKV(QKVN / 128, ROWS / 128);   // 24 x 32
    const dim3 gD(DMODEL / 128, ROWS / 128);   // 8 x 32
    const dim3 gF(FF / 128, ROWS / 128);       // 32 x 32
    const dim3 gA(SEQ / 64, BH);               // 32 x 32

    const float QSCL = 0.125f * 1.44269504088896f;  // 1/sqrt(64) * log2(e)

    for (int l = 0; l < LNUM; l++) {
        __half* lw = p_w + (size_t)l * LW;
        const float* vbq = bq + (size_t)l * DMODEL;
        const float* vbk = bk + (size_t)l * DMODEL;
        const float* vbv = bv + (size_t)l * DMODEL;
        const float* vbo = bo + (size_t)l * DMODEL;
        const float* vb1 = b1 + (size_t)l * FF;
        const float* vb2 = b2 + (size_t)l * DMODEL;

        // h = LN(out) -> fp16
        ln_h_kernel<<<ROWS, 256>>>(cur, gin, bin, p_h);

        // fused QKV projection (Q segment pre-scaled by softmax constant)
        mma_gemm<1><<<gQKV, 256, GSMEM>>>(p_h, lw + OFF_QKV, vbq, vbk, vbv,
                                          DMODEL, QSCL,
                                          nullptr, nullptr, p_qkv,
                                          ROWS, QKVN, DMODEL, 0);

        // fused attention -> ao fp16
        flash_mma<<<gA, 128, FLASH_SMEM>>>(p_qkv, p_ao);

        // out = res + ao @ Wo + bo (fp32)
        mma_gemm<0><<<gD, 256, GSMEM>>>(p_ao, lw + OFF_WO, vbo, vbo, vbo,
                                        DMODEL, 1.f, cur,
                                        bufs[bi], nullptr,
                                        ROWS, DMODEL, DMODEL, 0);
        cur = bufs[bi]; bi ^= 1;

        // FFN
        ln_h_kernel<<<ROWS, 256>>>(cur, gat, bat, p_h);
        mma_gemm<1><<<gF, 256, GSMEM>>>(p_h, lw + OFF_W1, vb1, vb1, vb1,
                                        FF, 1.f,
                                        nullptr, nullptr, p_ff,
                                        ROWS, FF, DMODEL, 1);
        mma_gemm<0><<<gD, 256, GSMEM>>>(p_ff, lw + OFF_W2, vb2, vb2, vb2,
                                        DMODEL, 1.f, cur,
                                        bufs[bi], nullptr,
                                        ROWS, DMODEL, FF, 0);
        cur = bufs[bi]; bi ^= 1;
    }

    ln_kernel<<<ROWS, 256>>>(cur, gou, bou, out);
}

// round 16
// speedup vs baseline: 1.0077x; 1.0077x over previous
#include <cuda_runtime.h>
#include <cuda_fp16.h>
#include <math.h>
#include <stdint.h>

// Problem constants
#define LNUM 2
#define HNUM 16
#define DMODEL 1024
#define FF 4096
#define BATCH 2
#define SEQ 2048
#define LN_EPS 1e-5f

#define ROWS (BATCH * SEQ)          // 4096
#define BH (BATCH * HNUM)           // 32
#define QKVN 3072

// per-layer transposed-weight layout inside g_w (in halves)
#define OFF_QKV 0
#define OFF_WO  (3u * 1024u * 1024u)
#define OFF_W1  (4u * 1024u * 1024u)
#define OFF_W2  (8u * 1024u * 1024u)
#define LW      (12u * 1024u * 1024u)

// ---------------- device scratch ----------------
__device__ float g_buf0[(size_t)ROWS * DMODEL];
__device__ float g_buf1[(size_t)ROWS * DMODEL];

__device__ __half g_h  [(size_t)ROWS * DMODEL];
__device__ __half g_qkv[(size_t)ROWS * QKVN];
__device__ __half g_ao [(size_t)ROWS * DMODEL];
__device__ __half g_ff [(size_t)ROWS * FF];
__device__ __half g_w  [(size_t)LNUM * LW];     // 24M halves = 48 MB

// ---------------- helpers ----------------
__device__ __forceinline__ uint32_t smem_u32(const void* p) {
    uint32_t a;
    asm("{ .reg .u64 t; cvta.to.shared.u64 t, %1; cvt.u32.u64 %0, t; }"
        : "=r"(a) : "l"(p));
    return a;
}

__device__ __forceinline__ void cp16(uint32_t dst, const void* src) {
    asm volatile("cp.async.cg.shared.global [%0], [%1], 16;"
                 :: "r"(dst), "l"(src));
}

__device__ __forceinline__ void ldm_x4(uint32_t addr, uint32_t r[4]) {
    asm volatile("ldmatrix.sync.aligned.m8n8.x4.shared.b16 {%0,%1,%2,%3}, [%4];"
                 : "=r"(r[0]), "=r"(r[1]), "=r"(r[2]), "=r"(r[3]) : "r"(addr));
}

__device__ __forceinline__ void ldm_x4_t(uint32_t addr, uint32_t r[4]) {
    asm volatile("ldmatrix.sync.aligned.m8n8.x4.trans.shared.b16 {%0,%1,%2,%3}, [%4];"
                 : "=r"(r[0]), "=r"(r[1]), "=r"(r[2]), "=r"(r[3]) : "r"(addr));
}

__device__ __forceinline__ void mma_f16(float d[4], const uint32_t a[4],
                                        const uint32_t b[2]) {
    asm volatile(
        "mma.sync.aligned.m16n8k16.row.col.f32.f16.f16.f32 "
        "{%0,%1,%2,%3}, {%4,%5,%6,%7}, {%8,%9}, {%0,%1,%2,%3};"
        : "+f"(d[0]), "+f"(d[1]), "+f"(d[2]), "+f"(d[3])
        : "r"(a[0]), "r"(a[1]), "r"(a[2]), "r"(a[3]), "r"(b[0]), "r"(b[1]));
}

__device__ __forceinline__ uint32_t pack_h2(float a, float b) {
    __half2 t = __floats2half2_rn(a, b);
    return *(uint32_t*)&t;
}

__device__ __forceinline__ void hstore2(__half* p, size_t off, float v0, float v1) {
    *(__half2*)(p + off) = __floats2half2_rn(v0, v1);
}

__device__ __forceinline__ float ex2f(float x) {
    float y;
    asm("ex2.approx.ftz.f32 %0, %1;" : "=f"(y) : "f"(x));
    return y;
}

#define CP_COMMIT() asm volatile("cp.async.commit_group;" ::: "memory")

// ---------------- batched weight transpose-cast (all layers, one launch) ----------------
#define NSEG 12

struct CastTable {
    const float* in[NSEG];
    long long outOff[NSEG];
    int Kdim[NSEG];
    int Ndim[NSEG];
    int tile0[NSEG];
};

__global__ void __launch_bounds__(256)
castAll_kernel(CastTable tab, __half* __restrict__ outBase)
{
    __shared__ float t[64][65];
    const int bid = blockIdx.x;
    int s = 0;
#pragma unroll
    for (int i = 1; i < NSEG; i++)
        if (bid >= tab.tile0[i]) s = i;

    const float* in = tab.in[s];
    __half* outT = outBase + tab.outOff[s];
    const int Kdim = tab.Kdim[s], Ndim = tab.Ndim[s];
    const int lt = bid - tab.tile0[s];
    const int tiles_x = Ndim >> 6;
    const int n0 = (lt % tiles_x) * 64, k0 = (lt / tiles_x) * 64;

    {
        const int tx = threadIdx.x & 15, ty = threadIdx.x >> 4;
#pragma unroll
        for (int j = 0; j < 4; j++) {
            const int k = ty + j * 16;
            float4 v = *(const float4*)(in + (size_t)(k0 + k) * Ndim + n0 + tx * 4);
            t[k][tx * 4 + 0] = v.x;
            t[k][tx * 4 + 1] = v.y;
            t[k][tx * 4 + 2] = v.z;
            t[k][tx * 4 + 3] = v.w;
        }
    }
    __syncthreads();
    {
        const int tx = threadIdx.x & 31, ty = threadIdx.x >> 5;
#pragma unroll
        for (int j = 0; j < 8; j++) {
            const int n = ty + j * 8;
            __half2 h = __floats2half2_rn(t[tx * 2][n], t[tx * 2 + 1][n]);
            *(__half2*)(outT + (size_t)(n0 + n) * Kdim + k0 + tx * 2) = h;
        }
    }
}

// ---------------- fp16 tensor-core GEMM, 4-stage cp.async ring, K-chunk 32 ----------------
// OMODE 0: Cf = acc + bias (+res), fp32.   OMODE 1: Ch = fp16(scl*(relu?(acc+bias))).
#define TILEB (128 * 80)               // 10240 B
#define STAGEB (2 * TILEB)             // 20480 B
#define GSMEM (4 * STAGEB)             // 81920 B

template <int OMODE>
__global__ void __launch_bounds__(256, 2)
mma_gemm(const __half* __restrict__ A, const __half* __restrict__ B,
         const float* __restrict__ bias0, const float* __restrict__ bias1,
         const float* __restrict__ bias2, int biasSeg, float scl0,
         const float* __restrict__ res,
         float* __restrict__ Cf, __half* __restrict__ Ch,
         int M, int N, int K, int relu)
{
    extern __shared__ char smem[];
    const uint32_t sb = smem_u32(smem);

    const int tid = threadIdx.x, wid = tid >> 5, lane = tid & 31;
    const int bm = blockIdx.y * 128, bn = blockIdx.x * 128;
    const int wm = wid >> 2, wn = wid & 3;     // warp tile 64 x 32

    const __half* sA = A + (size_t)bm * K;
    const __half* sB = B + (size_t)bn * K;

    const int r0 = (tid * 2) >> 2, c0 = (tid * 2) & 3;
    const int r1 = (tid * 2 + 1) >> 2, c1 = (tid * 2 + 1) & 3;

    const int NC = K >> 5;

#define ISSUE_CHUNK(c)                                                      \
    do {                                                                    \
        const uint32_t st_ = sb + ((c) & 3) * STAGEB;                       \
        const int kc_ = (c) << 5;                                           \
        cp16(st_ + r0 * 80 + c0 * 16, sA + (size_t)r0 * K + kc_ + c0 * 8);  \
        cp16(st_ + r1 * 80 + c1 * 16, sA + (size_t)r1 * K + kc_ + c1 * 8);  \
        cp16(st_ + TILEB + r0 * 80 + c0 * 16,                               \
             sB + (size_t)r0 * K + kc_ + c0 * 8);                           \
        cp16(st_ + TILEB + r1 * 80 + c1 * 16,                               \
             sB + (size_t)r1 * K + kc_ + c1 * 8);                           \
        CP_COMMIT();                                                        \
    } while (0)

    ISSUE_CHUNK(0);
    ISSUE_CHUNK(1);
    ISSUE_CHUNK(2);

    float d[4][4][4];
#pragma unroll
    for (int i = 0; i < 4; i++)
#pragma unroll
        for (int j = 0; j < 4; j++)
#pragma unroll
            for (int q = 0; q < 4; q++) d[i][j][q] = 0.f;

    const uint32_t arow = (uint32_t)(wm * 64 + (lane & 15));
    const uint32_t abyte = (uint32_t)((lane >> 4) * 16);
    const uint32_t bnr = (uint32_t)(wn * 32 + (lane & 7) + 8 * ((lane >> 4) & 1));
    const uint32_t bkb = (uint32_t)(((lane >> 3) & 1) * 16);

    for (int c = 0; c < NC; c++) {
        if (c + 3 <= NC) {
            asm volatile("cp.async.wait_group 2;" ::: "memory");
        } else if (c + 2 == NC) {
            asm volatile("cp.async.wait_group 1;" ::: "memory");
        } else {
            asm volatile("cp.async.wait_group 0;" ::: "memory");
        }
        __syncthreads();
        if (c + 3 < NC) ISSUE_CHUNK(c + 3);

        const uint32_t st = sb + (c & 3) * STAGEB;
#pragma unroll
        for (int k16 = 0; k16 < 2; k16++) {
            uint32_t af[4][4], bfr[4][2];
#pragma unroll
            for (int i = 0; i < 4; i++)
                ldm_x4(st + (arow + i * 16) * 80 + k16 * 32 + abyte, af[i]);
#pragma unroll
            for (int nb = 0; nb < 2; nb++) {
                uint32_t r[4];
                ldm_x4(st + TILEB + (bnr + nb * 16) * 80 + k16 * 32 + bkb, r);
                bfr[nb * 2 + 0][0] = r[0]; bfr[nb * 2 + 0][1] = r[1];
                bfr[nb * 2 + 1][0] = r[2]; bfr[nb * 2 + 1][1] = r[3];
            }
#pragma unroll
            for (int i = 0; i < 4; i++)
#pragma unroll
                for (int j = 0; j < 4; j++)
                    mma_f16(d[i][j], af[i], bfr[j]);
        }
    }
#undef ISSUE_CHUNK

    // epilogue
    const int seg = bn / biasSeg;
    const float* bp = (seg == 0) ? bias0 : ((seg == 1) ? bias1 : bias2);
    const float scl = (seg == 0) ? scl0 : 1.f;
    const int bcol0 = bn - seg * biasSeg;
    const int er = lane >> 2, ec = 2 * (lane & 3);
#pragma unroll
    for (int i = 0; i < 4; i++) {
#pragma unroll
        for (int rr = 0; rr < 2; rr++) {
            const int grow = bm + wm * 64 + i * 16 + er + rr * 8;
#pragma unroll
            for (int j = 0; j < 4; j++) {
                const int coff = wn * 32 + j * 8 + ec;
                const int gcol = bn + coff;
                float v0 = d[i][j][rr * 2 + 0] + bp[bcol0 + coff];
                float v1 = d[i][j][rr * 2 + 1] + bp[bcol0 + coff + 1];
                if (relu) { v0 = fmaxf(v0, 0.f); v1 = fmaxf(v1, 0.f); }
                if (OMODE == 0) {
                    if (res) {
                        v0 += res[(size_t)grow * N + gcol];
                        v1 += res[(size_t)grow * N + gcol + 1];
                    }
                    *(float2*)(Cf + (size_t)grow * N + gcol) = make_float2(v0, v1);
                } else {
                    hstore2(Ch, (size_t)grow * N + gcol, v0 * scl, v1 * scl);
                }
            }
        }
    }
}

// ---------------- LayerNorm -> fp16 ----------------
__global__ void __launch_bounds__(256)
ln_h_kernel(const float* __restrict__ in, const float* __restrict__ gamma,
            const float* __restrict__ beta, __half* __restrict__ out)
{
    const int row = blockIdx.x;
    const float* x = in + (size_t)row * DMODEL;
    const int tid = threadIdx.x;

    float4 v4 = *(const float4*)(x + tid * 4);
    float v[4] = {v4.x, v4.y, v4.z, v4.w};
    float s = 0.f, ss = 0.f;
#pragma unroll
    for (int j = 0; j < 4; j++) { s += v[j]; ss += v[j] * v[j]; }
#pragma unroll
    for (int o2 = 16; o2 > 0; o2 >>= 1) {
        s  += __shfl_xor_sync(0xffffffffu, s,  o2);
        ss += __shfl_xor_sync(0xffffffffu, ss, o2);
    }
    __shared__ float red[18];
    const int warp = tid >> 5, lane = tid & 31;
    if (lane == 0) { red[warp] = s; red[warp + 8] = ss; }
    __syncthreads();
    if (tid == 0) {
        float ts = 0.f, tss = 0.f;
#pragma unroll
        for (int w = 0; w < 8; w++) { ts += red[w]; tss += red[w + 8]; }
        float mu = ts / (float)DMODEL;
        float var = tss / (float)DMODEL - mu * mu;
        red[16] = mu;
        red[17] = rsqrtf(var + LN_EPS);
    }
    __syncthreads();
    const float mu = red[16], rstd = red[17];
    float y[4];
#pragma unroll
    for (int j = 0; j < 4; j++) {
        int idx = tid * 4 + j;
        y[j] = (v[j] - mu) * rstd * gamma[idx] + beta[idx];
    }
    hstore2(out, (size_t)row * DMODEL + tid * 4,     y[0], y[1]);
    hstore2(out, (size_t)row * DMODEL + tid * 4 + 2, y[2], y[3]);
}

// ---------------- Final LayerNorm (fp32 out) ----------------
__global__ void __launch_bounds__(256)
ln_kernel(const float* __restrict__ in, const float* __restrict__ gamma,
          const float* __restrict__ beta, float* __restrict__ out)
{
    const int row = blockIdx.x;
    const float* x = in + (size_t)row * DMODEL;
    float* o = out + (size_t)row * DMODEL;
    const int tid = threadIdx.x;

    float v[4];
    float s = 0.f, ss = 0.f;
#pragma unroll
    for (int j = 0; j < 4; j++) {
        v[j] = x[tid + j * 256];
        s += v[j];
        ss += v[j] * v[j];
    }
#pragma unroll
    for (int o2 = 16; o2 > 0; o2 >>= 1) {
        s  += __shfl_xor_sync(0xffffffffu, s,  o2);
        ss += __shfl_xor_sync(0xffffffffu, ss, o2);
    }
    __shared__ float red[18];
    const int warp = tid >> 5, lane = tid & 31;
    if (lane == 0) { red[warp] = s; red[warp + 8] = ss; }
    __syncthreads();
    if (tid == 0) {
        float ts = 0.f, tss = 0.f;
#pragma unroll
        for (int w = 0; w < 8; w++) { ts += red[w]; tss += red[w + 8]; }
        float mu = ts / (float)DMODEL;
        float var = tss / (float)DMODEL - mu * mu;
        red[16] = mu;
        red[17] = rsqrtf(var + LN_EPS);
    }
    __syncthreads();
    const float mu = red[16], rstd = red[17];
#pragma unroll
    for (int j = 0; j < 4; j++) {
        int idx = tid + j * 256;
        o[idx] = (v[j] - mu) * rstd * gamma[idx] + beta[idx];
    }
}

// ---------------- Flash attention: Q-block 64, 128 threads, Q in registers ----------------
// Q pre-scaled (log2 domain). smem: 2 stages of (K 9216 + V 9216) = 36864 B.
// Q is staged through stage-0's K area once, ldmatrix'd to registers, then overwritten.
#define F_STGB 18432
#define FLASH_SMEM (2 * F_STGB)   // 36864

__global__ void __launch_bounds__(128, 4)
flash_mma(const __half* __restrict__ qkv, __half* __restrict__ ao)
{
    extern __shared__ char smem[];
    const uint32_t sb = smem_u32(smem);

    const int qb = blockIdx.x, bh = blockIdx.y;
    const int b = bh >> 4, h = bh & 15;
    const int tid = threadIdx.x, wid = tid >> 5, lane = tid & 31;

    const size_t qrow0 = (size_t)b * SEQ + (size_t)qb * 64;
    const __half* qp = qkv + qrow0 * QKVN + h * 64;
    const __half* kp = qkv + (size_t)b * SEQ * QKVN + 1024 + h * 64;
    const __half* vp = qkv + (size_t)b * SEQ * QKVN + 2048 + h * 64;

    const uint32_t acol = (uint32_t)(16 * (lane >> 4));
    const uint32_t bn_row = (uint32_t)(((lane & 7) + 8 * ((lane >> 4) & 1)) * 144);
    const uint32_t bkb = (uint32_t)(16 * ((lane >> 3) & 1));
    const uint32_t v_row = (uint32_t)(((lane & 7) + 8 * ((lane >> 3) & 1)) * 144);
    const uint32_t v_db = (uint32_t)(16 * ((lane >> 4) & 1));

    // ---- stage Q through stage-0 K area, load fragments to registers ----
#pragma unroll
    for (int it = 0; it < 4; it++) {
        int f = tid + it * 128;
        int r = f >> 3, ch = f & 7;
        cp16(sb + r * 144 + ch * 16, qp + (size_t)r * QKVN + ch * 8);
    }
    CP_COMMIT();
    asm volatile("cp.async.wait_group 0;" ::: "memory");
    __syncthreads();

    uint32_t qf[4][4];
    {
        const uint32_t qrow = sb + (wid * 16 + (lane & 15)) * 144;
#pragma unroll
        for (int t = 0; t < 4; t++)
            ldm_x4(qrow + t * 32 + acol, qf[t]);
    }
    __syncthreads();   // all warps done reading Q before K/V overwrite

    // ---- stage K/V tile 0 (overwrites Q staging) ----
#pragma unroll
    for (int it = 0; it < 4; it++) {
        int f = tid + it * 128;
        int r = f >> 3, ch = f & 7;
        uint32_t dst = sb + r * 144 + ch * 16;
        size_t go = (size_t)r * QKVN + ch * 8;
        cp16(dst, kp + go);
        cp16(dst + 9216, vp + go);
    }
    CP_COMMIT();

    float o[8][4];
#pragma unroll
    for (int j = 0; j < 8; j++)
#pragma unroll
        for (int q = 0; q < 4; q++) o[j][q] = 0.f;
    float m0 = -INFINITY, m1 = -INFINITY, l0 = 0.f, l1 = 0.f;

    for (int kt = 0; kt < SEQ / 64; kt++) {
        asm volatile("cp.async.wait_group 0;" ::: "memory");
        __syncthreads();

        if (kt + 1 < SEQ / 64) {
            uint32_t st = sb + ((kt + 1) & 1) * F_STGB;
            size_t rbase = (size_t)(kt + 1) * 64;
#pragma unroll
            for (int it = 0; it < 4; it++) {
                int f = tid + it * 128;
                int r = f >> 3, ch = f & 7;
                uint32_t dst = st + r * 144 + ch * 16;
                size_t go = (rbase + r) * QKVN + ch * 8;
                cp16(dst, kp + go);
                cp16(dst + 9216, vp + go);
            }
            CP_COMMIT();
        }

        const uint32_t kst = sb + (kt & 1) * F_STGB;

        // ---- S = Q K^T (Q fragments in registers) ----
        float s[8][4];
#pragma unroll
        for (int j = 0; j < 8; j++)
#pragma unroll
            for (int q = 0; q < 4; q++) s[j][q] = 0.f;

#pragma unroll
        for (int t = 0; t < 4; t++) {
            uint32_t kbase = kst + bn_row + t * 32 + bkb;
#pragma unroll
            for (int nb = 0; nb < 4; nb++) {
                uint32_t r[4];
                ldm_x4(kbase + nb * 16 * 144, r);
                mma_f16(s[nb * 2],     qf[t], &r[0]);
                mma_f16(s[nb * 2 + 1], qf[t], &r[2]);
            }
        }

        // ---- online softmax (base-2, pre-scaled) ----
        float mx0 = -INFINITY, mx1 = -INFINITY;
#pragma unroll
        for (int j = 0; j < 8; j++) {
            mx0 = fmaxf(mx0, fmaxf(s[j][0], s[j][1]));
            mx1 = fmaxf(mx1, fmaxf(s[j][2], s[j][3]));
        }
        mx0 = fmaxf(mx0, __shfl_xor_sync(0xffffffffu, mx0, 1));
        mx0 = fmaxf(mx0, __shfl_xor_sync(0xffffffffu, mx0, 2));
        mx1 = fmaxf(mx1, __shfl_xor_sync(0xffffffffu, mx1, 1));
        mx1 = fmaxf(mx1, __shfl_xor_sync(0xffffffffu, mx1, 2));
        const float mn0 = fmaxf(m0, mx0), mn1 = fmaxf(m1, mx1);
        const float c0 = ex2f(m0 - mn0), c1 = ex2f(m1 - mn1);
        float rs0 = 0.f, rs1 = 0.f;
#pragma unroll
        for (int j = 0; j < 8; j++) {
            s[j][0] = ex2f(s[j][0] - mn0);
            s[j][1] = ex2f(s[j][1] - mn0);
            s[j][2] = ex2f(s[j][2] - mn1);
            s[j][3] = ex2f(s[j][3] - mn1);
            rs0 += s[j][0] + s[j][1];
            rs1 += s[j][2] + s[j][3];
        }
        rs0 += __shfl_xor_sync(0xffffffffu, rs0, 1);
        rs0 += __shfl_xor_sync(0xffffffffu, rs0, 2);
        rs1 += __shfl_xor_sync(0xffffffffu, rs1, 1);
        rs1 += __shfl_xor_sync(0xffffffffu, rs1, 2);
        if (c0 != 1.f) {
            l0 *= c0;
#pragma unroll
            for (int j = 0; j < 8; j++) { o[j][0] *= c0; o[j][1] *= c0; }
        }
        if (c1 != 1.f) {
            l1 *= c1;
#pragma unroll
            for (int j = 0; j < 8; j++) { o[j][2] *= c1; o[j][3] *= c1; }
        }
        l0 += rs0;
        l1 += rs1;
        m0 = mn0; m1 = mn1;

        // ---- O += P V ----
        const uint32_t vst = kst + 9216;
#pragma unroll
        for (int t = 0; t < 4; t++) {
            uint32_t pa[4];
            pa[0] = pack_h2(s[2 * t][0],     s[2 * t][1]);
            pa[1] = pack_h2(s[2 * t][2],     s[2 * t][3]);
            pa[2] = pack_h2(s[2 * t + 1][0], s[2 * t + 1][1]);
            pa[3] = pack_h2(s[2 * t + 1][2], s[2 * t + 1][3]);
            uint32_t vbase = vst + t * 16 * 144 + v_row + v_db;
#pragma unroll
            for (int nb = 0; nb < 4; nb++) {
                uint32_t r[4];
                ldm_x4_t(vbase + nb * 32, r);
                mma_f16(o[nb * 2],     pa, &r[0]);
                mma_f16(o[nb * 2 + 1], pa, &r[2]);
            }
        }
    }

    const float inv0 = 1.f / l0, inv1 = 1.f / l1;
    const size_t row0 = qrow0 + wid * 16 + (lane >> 2);
    const int colb = h * 64 + 2 * (lane & 3);
#pragma unroll
    for (int j = 0; j < 8; j++) {
        hstore2(ao, row0 * DMODEL + colb + j * 8,       o[j][0] * inv0, o[j][1] * inv0);
        hstore2(ao, (row0 + 8) * DMODEL + colb + j * 8, o[j][2] * inv1, o[j][3] * inv1);
    }
}

// ---------------- host orchestration ----------------
extern "C" void kernel_launch(void* const* d_in, const int* in_sizes, int n_in,
                              void* d_out, int out_size)
{
    (void)in_sizes; (void)n_in; (void)out_size;
    const float* x    = (const float*)d_in[0];
    const float* Wq   = (const float*)d_in[1];
    const float* bq   = (const float*)d_in[2];
    const float* Wk   = (const float*)d_in[3];
    const float* bk   = (const float*)d_in[4];
    const float* Wv   = (const float*)d_in[5];
    const float* bv   = (const float*)d_in[6];
    const float* Wo   = (const float*)d_in[7];
    const float* bo   = (const float*)d_in[8];
    const float* W1   = (const float*)d_in[9];
    const float* b1   = (const float*)d_in[10];
    const float* W2   = (const float*)d_in[11];
    const float* b2   = (const float*)d_in[12];
    const float* gin  = (const float*)d_in[13];
    const float* bin  = (const float*)d_in[14];
    const float* gat  = (const float*)d_in[15];
    const float* bat  = (const float*)d_in[16];
    const float* gou  = (const float*)d_in[17];
    const float* bou  = (const float*)d_in[18];
    float* out = (float*)d_out;

    cudaFuncSetAttribute(mma_gemm<0>,
                         cudaFuncAttributeMaxDynamicSharedMemorySize, GSMEM);
    cudaFuncSetAttribute(mma_gemm<1>,
                         cudaFuncAttributeMaxDynamicSharedMemorySize, GSMEM);
    cudaFuncSetAttribute(flash_mma,
                         cudaFuncAttributeMaxDynamicSharedMemorySize, FLASH_SMEM);

    float *p_b0, *p_b1;
    __half *p_h, *p_qkv, *p_ao, *p_ff, *p_w;
    cudaGetSymbolAddress((void**)&p_b0,  g_buf0);
    cudaGetSymbolAddress((void**)&p_b1,  g_buf1);
    cudaGetSymbolAddress((void**)&p_h,   g_h);
    cudaGetSymbolAddress((void**)&p_qkv, g_qkv);
    cudaGetSymbolAddress((void**)&p_ao,  g_ao);
    cudaGetSymbolAddress((void**)&p_ff,  g_ff);
    cudaGetSymbolAddress((void**)&p_w,   g_w);

    // ---- one batched transpose-cast for ALL weights of BOTH layers ----
    {
        CastTable tab;
        int t0 = 0;
        for (int l = 0; l < LNUM; l++) {
            const int base = l * 6;
            const float* wsrc[6] = {
                Wq + (size_t)l * DMODEL * DMODEL,
                Wk + (size_t)l * DMODEL * DMODEL,
                Wv + (size_t)l * DMODEL * DMODEL,
                Wo + (size_t)l * DMODEL * DMODEL,
                W1 + (size_t)l * DMODEL * FF,
                W2 + (size_t)l * FF * DMODEL };
            const long long woff[6] = {
                (long long)l * LW + OFF_QKV,
                (long long)l * LW + OFF_QKV + (long long)DMODEL * DMODEL,
                (long long)l * LW + OFF_QKV + 2LL * DMODEL * DMODEL,
                (long long)l * LW + OFF_WO,
                (long long)l * LW + OFF_W1,
                (long long)l * LW + OFF_W2 };
            const int kk[6] = {DMODEL, DMODEL, DMODEL, DMODEL, DMODEL, FF};
            const int nn[6] = {DMODEL, DMODEL, DMODEL, DMODEL, FF, DMODEL};
            for (int i = 0; i < 6; i++) {
                tab.in[base + i] = wsrc[i];
                tab.outOff[base + i] = woff[i];
                tab.Kdim[base + i] = kk[i];
                tab.Ndim[base + i] = nn[i];
                tab.tile0[base + i] = t0;
                t0 += (kk[i] >> 6) * (nn[i] >> 6);
            }
        }
        castAll_kernel<<<t0, 256>>>(tab, p_w);
    }

    // residual rotation: layer-0 residual read directly from x (no memcpy)
    const float* cur = x;
    float* bufs[2] = {p_b0, p_b1};
    int bi = 0;

    const dim3 gQKV(QKVN / 128, ROWS / 128);   // 24 x 32
    const dim3 gD(DMODEL / 128, ROWS / 128);   // 8 x 32
    const dim3 gF(FF / 128, ROWS / 128);       // 32 x 32
    const dim3 gA(SEQ / 64, BH);               // 32 x 32

    const float QSCL = 0.125f * 1.44269504088896f;  // 1/sqrt(64) * log2(e)

    for (int l = 0; l < LNUM; l++) {
        __half* lw = p_w + (size_t)l * LW;
        const float* vbq = bq + (size_t)l * DMODEL;
        const float* vbk = bk + (size_t)l * DMODEL;
        const float* vbv = bv + (size_t)l * DMODEL;
        const float* vbo = bo + (size_t)l * DMODEL;
        const float* vb1 = b1 + (size_t)l * FF;
        const float* vb2 = b2 + (size_t)l * DMODEL;

        // h = LN(out) -> fp16
        ln_h_kernel<<<ROWS, 256>>>(cur, gin, bin, p_h);

        // fused QKV projection (Q segment pre-scaled by softmax constant)
        mma_gemm<1><<<gQKV, 256, GSMEM>>>(p_h, lw + OFF_QKV, vbq, vbk, vbv,
                                          DMODEL, QSCL,
                                          nullptr, nullptr, p_qkv,
                                          ROWS, QKVN, DMODEL, 0);

        // fused attention -> ao fp16
        flash_mma<<<gA, 128, FLASH_SMEM>>>(p_qkv, p_ao);

        // out = res + ao @ Wo + bo (fp32)
        mma_gemm<0><<<gD, 256, GSMEM>>>(p_ao, lw + OFF_WO, vbo, vbo, vbo,
                                        DMODEL, 1.f, cur,
                                        bufs[bi], nullptr,
                                        ROWS, DMODEL, DMODEL, 0);
        cur = bufs[bi]; bi ^= 1;

        // FFN
        ln_h_kernel<<<ROWS, 256>>>(cur, gat, bat, p_h);
        mma_gemm<1><<<gF, 256, GSMEM>>>(p_h, lw + OFF_W1, vb1, vb1, vb1,
                                        FF, 1.f,
                                        nullptr, nullptr, p_ff,
                                        ROWS, FF, DMODEL, 1);
        mma_gemm<0><<<gD, 256, GSMEM>>>(p_ff, lw + OFF_W2, vb2, vb2, vb2,
                                        DMODEL, 1.f, cur,
                                        bufs[bi], nullptr,
                                        ROWS, DMODEL, FF, 0);
        cur = bufs[bi]; bi ^= 1;
    }

    ln_kernel<<<ROWS, 256>>>(cur, gou, bou, out);
}